// round 7
// baseline (speedup 1.0000x reference)
#include <cuda_runtime.h>
#include <cuda_bf16.h>
#include <math_constants.h>
#include <cstdint>

// Problem shape (fixed by the reference)
#define NN 8192
#define DD 512

// GEMM tiling (int8: 1 byte/elem, feature row = 512 B)
#define BM 128
#define BN 128
#define BKB 128               // K bytes per smem stage (= 128 int8)
#define NKITER (DD / BKB)     // 4
#define NTHREADS 256
#define NSTAGE 3
#define NCHUNK 256            // stats chunk width = 32 cols

// smem: 3 stages of 2 tiles (A,B), each 128 rows x 144 bytes (128B data + 16B pad)
#define ROWB 144
#define TILE_B (128 * ROWB)        // 18432
#define S_A 0
#define S_B TILE_B
#define STAGE_B (2 * TILE_B)       // 36864
#define SMEM_LAB_A 0               // 128 ints
#define SMEM_LAB_B 512
#define SMEM_SA 1024               // 128 floats (row dequant scales)
#define SMEM_SB 1536
#define SMEM_STAGE0 2048
#define SMEM_TOTAL (SMEM_STAGE0 + NSTAGE * STAGE_B)   // 112640 (2 CTAs/SM)

// ---------------- device scratch (no cudaMalloc allowed) ----------------
__device__ int8_t gA[NN * DD];
__device__ int8_t gB[NN * DD];
__device__ float  g_s[2 * NN];      // dequant scales: [0..NN) A rows, [NN..2NN) B rows
__device__ float g_m [NCHUNK * NN];
__device__ float g_l [NCHUNK * NN];
__device__ float g_ms[NCHUNK * NN];
__device__ int   g_c [NCHUNK * NN];
__device__ int   g_lab[NN];

// ---------------- PTX helpers (baseline sm_80+ features only) ----------------
__device__ __forceinline__ uint32_t smem_u32(const void* p) {
    uint32_t a;
    asm("{ .reg .u64 t; cvta.to.shared.u64 t, %1; cvt.u32.u64 %0, t; }" : "=r"(a) : "l"(p));
    return a;
}
#define CPA16(dst, src) \
    asm volatile("cp.async.cg.shared.global [%0], [%1], 16;" :: "r"(dst), "l"(src))
#define CPA_COMMIT() asm volatile("cp.async.commit_group;" ::: "memory")
#define CPA_WAIT(n)  asm volatile("cp.async.wait_group %0;" :: "n"(n) : "memory")

__device__ __forceinline__ void ldsm4(uint32_t (&r)[4], uint32_t addr) {
    asm volatile("ldmatrix.sync.aligned.m8n8.x4.shared.b16 {%0,%1,%2,%3}, [%4];"
                 : "=r"(r[0]), "=r"(r[1]), "=r"(r[2]), "=r"(r[3]) : "r"(addr));
}
// s8 x s8 -> s32, m16n8k32 (2048 MACs per instruction)
__device__ __forceinline__ void mma_s8(int (&c)[4], const uint32_t (&a)[4],
                                       uint32_t b0, uint32_t b1) {
    asm volatile(
        "mma.sync.aligned.m16n8k32.row.col.s32.s8.s8.s32 "
        "{%0,%1,%2,%3}, {%4,%5,%6,%7}, {%8,%9}, {%0,%1,%2,%3};"
        : "+r"(c[0]), "+r"(c[1]), "+r"(c[2]), "+r"(c[3])
        : "r"(a[0]), "r"(a[1]), "r"(a[2]), "r"(a[3]), "r"(b0), "r"(b1));
}

// ---------------- label normalization (int32 vs int64 ambiguity) ----------------
__global__ void prep_labels(const void* __restrict__ labels_raw) {
    __shared__ int s_is64;
    if (threadIdx.x == 0) {
        const unsigned long long* p = (const unsigned long long*)labels_raw;
        int is64 = 1;
        for (int w = 0; w < 32; w++)
            if ((p[w] >> 32) != 0ull) { is64 = 0; break; }
        s_is64 = is64;
    }
    __syncthreads();
    const int is64 = s_is64;
    const long long* p64 = (const long long*)labels_raw;
    const int*       p32 = (const int*)labels_raw;
    for (int i = threadIdx.x; i < NN; i += blockDim.x)
        g_lab[i] = is64 ? (int)p64[i] : p32[i];
}

__global__ void zero_out(float* out) { if (threadIdx.x == 0) out[0] = 0.0f; }

// ---------------- fp32 -> int8 row-absmax quantization ----------------
// One warp per feature row (512 floats). grid 2048 x 256 (8 warps/block).
__global__ void quant_s8(const float* __restrict__ A, const float* __restrict__ B) {
    const int w = blockIdx.x * 8 + (threadIdx.x >> 5);   // 0..16383
    const int lane = threadIdx.x & 31;
    const bool isA = (w < NN);
    const float* src = isA ? (A + (size_t)w * DD) : (B + (size_t)(w - NN) * DD);

    float4 v[4];
    #pragma unroll
    for (int i = 0; i < 4; i++) v[i] = ((const float4*)src)[lane * 4 + i];

    float mx = 0.0f;
    #pragma unroll
    for (int i = 0; i < 4; i++) {
        mx = fmaxf(mx, fmaxf(fmaxf(fabsf(v[i].x), fabsf(v[i].y)),
                             fmaxf(fabsf(v[i].z), fabsf(v[i].w))));
    }
    #pragma unroll
    for (int o = 16; o >= 1; o >>= 1)
        mx = fmaxf(mx, __shfl_xor_sync(0xffffffffu, mx, o));

    const float inv = (mx > 0.0f) ? (127.0f / mx) : 0.0f;

    int q[16];
    #pragma unroll
    for (int i = 0; i < 4; i++) {
        q[i * 4 + 0] = __float2int_rn(v[i].x * inv);
        q[i * 4 + 1] = __float2int_rn(v[i].y * inv);
        q[i * 4 + 2] = __float2int_rn(v[i].z * inv);
        q[i * 4 + 3] = __float2int_rn(v[i].w * inv);
    }
    int4 packed;
    int* pw = (int*)&packed;
    #pragma unroll
    for (int g = 0; g < 4; g++) {
        int a0 = max(-127, min(127, q[g * 4 + 0]));
        int a1 = max(-127, min(127, q[g * 4 + 1]));
        int a2 = max(-127, min(127, q[g * 4 + 2]));
        int a3 = max(-127, min(127, q[g * 4 + 3]));
        pw[g] = (a0 & 0xff) | ((a1 & 0xff) << 8) | ((a2 & 0xff) << 16) | (a3 << 24);
    }
    int8_t* dst = isA ? gA : gB;
    const int row = isA ? w : (w - NN);
    ((int4*)(dst + (size_t)row * DD))[lane] = packed;
    if (lane == 0) g_s[w] = mx * (1.0f / 127.0f);
}

// ---------------- GEMM building blocks ----------------
// Stage load: 2 tiles of 128 rows x 128B = 1024 x 16B chunks per tile,
// 256 threads -> 4 chunks per thread per tile. gmem row stride = 512 B.
__device__ __forceinline__ void load_stage(uint32_t sbase, int slot, int ki,
                                           int by, int bx, int tid) {
    const uint32_t stg = sbase + SMEM_STAGE0 + slot * STAGE_B;
    const int kb = ki * BKB;
    #pragma unroll
    for (int j = 0; j < 4; j++) {
        const int c = tid + j * 256;  // 0..1023
        const int r = c >> 3, q = c & 7;
        const uint32_t so = (uint32_t)(r * ROWB + q * 16);
        const size_t gAo = (size_t)(by * BM + r) * DD + kb + q * 16;
        const size_t gBo = (size_t)(bx * BN + r) * DD + kb + q * 16;
        CPA16(stg + S_A + so, (const char*)gA + gAo);
        CPA16(stg + S_B + so, (const char*)gB + gBo);
    }
}

// Warp tile 64(M) x 32(N); 4 k32-steps per stage; 16 IMMA per ks.
// ldmatrix.b16 fragments map 1:1 onto s8 k32 fragments (16B row-halves).
__device__ __forceinline__ void compute_stage(uint32_t stg, int wm, int wn, int lane,
                                              int (&acc)[4][4][4]) {
    #pragma unroll
    for (int ks = 0; ks < 4; ks++) {
        uint32_t a[4][4], b[2][4];
        const uint32_t a_lane = (uint32_t)((wm * 64 + (lane & 15)) * ROWB +
                                           ((lane >> 4) << 4) + ks * 32);
        #pragma unroll
        for (int mt = 0; mt < 4; mt++)
            ldsm4(a[mt], stg + S_A + a_lane + mt * 16 * ROWB);
        const uint32_t b_lane = (uint32_t)((wn * 32 + ((lane >> 4) & 1) * 8 + (lane & 7)) * ROWB +
                                           (((lane >> 3) & 1) << 4) + ks * 32);
        #pragma unroll
        for (int ntp = 0; ntp < 2; ntp++)
            ldsm4(b[ntp], stg + S_B + b_lane + ntp * 16 * ROWB);
        #pragma unroll
        for (int mt = 0; mt < 4; mt++)
            #pragma unroll
            for (int nt = 0; nt < 4; nt++) {
                const int ntp = nt >> 1, s2 = (nt & 1) * 2;
                mma_s8(acc[mt][nt], a[mt], b[ntp][s2], b[ntp][s2 + 1]);
            }
    }
}

// ---------------- fused GEMM + stats ----------------
__global__ void __launch_bounds__(NTHREADS, 2)
gemm_mma(const float* __restrict__ scale_p)
{
    extern __shared__ char smem[];
    const uint32_t sbase = smem_u32(smem);
    const int tid = threadIdx.x;
    const int wid = tid >> 5, lane = tid & 31;
    const int wm = wid >> 2, wn = wid & 3;      // 2x4 warp grid, tile 64x32
    const int bx = blockIdx.x, by = blockIdx.y;

    int*   labA = (int*)(smem + SMEM_LAB_A);
    int*   labB = (int*)(smem + SMEM_LAB_B);
    float* sSA  = (float*)(smem + SMEM_SA);
    float* sSB  = (float*)(smem + SMEM_SB);
    if (tid < 128) {
        labA[tid] = g_lab[by * BM + tid];
        sSA[tid]  = g_s[by * BM + tid];
    } else {
        labB[tid - 128] = g_lab[bx * BN + (tid - 128)];
        sSB[tid - 128]  = g_s[NN + bx * BN + (tid - 128)];
    }

    // prologue: 2 stages in flight
    load_stage(sbase, 0, 0, by, bx, tid); CPA_COMMIT();
    load_stage(sbase, 1, 1, by, bx, tid); CPA_COMMIT();

    int acc[4][4][4];
    #pragma unroll
    for (int a = 0; a < 4; a++)
        #pragma unroll
        for (int b = 0; b < 4; b++)
            #pragma unroll
            for (int e = 0; e < 4; e++) acc[a][b][e] = 0;

    // single-sync 3-stage pipeline over 4 k-iters
    #pragma unroll 1
    for (int i = 0; i < NKITER; i++) {
        if (i < NKITER - 1) CPA_WAIT(1);
        else                CPA_WAIT(0);
        __syncthreads();
        if (i + 2 < NKITER) { load_stage(sbase, (i + 2) % NSTAGE, i + 2, by, bx, tid); CPA_COMMIT(); }
        compute_stage(sbase + SMEM_STAGE0 + (i % NSTAGE) * STAGE_B, wm, wn, lane, acc);
    }

    // ---------------- epilogue: per-row stats over this warp's 32 columns ----------------
    const float s = *scale_p;
    const int chunk = bx * 4 + wn;
    const int colb = bx * BN + wn * 32 + (lane & 3) * 2;

    // dequant scales for this lane's 8 columns
    float sbv[8];
    #pragma unroll
    for (int j = 0; j < 8; j++)
        sbv[j] = sSB[wn * 32 + (j >> 1) * 8 + (lane & 3) * 2 + (j & 1)];

    #pragma unroll
    for (int mt = 0; mt < 4; mt++) {
        #pragma unroll
        for (int half = 0; half < 2; half++) {
            const int rloc = wm * 64 + mt * 16 + (lane >> 2) + half * 8;
            const int gy = by * BM + rloc;
            const int labr = labA[rloc];
            const float fs = sSA[rloc] * s;

            float v[8];
            #pragma unroll
            for (int nt = 0; nt < 4; nt++) {
                v[nt * 2 + 0] = (float)acc[mt][nt][half * 2 + 0] * fs * sbv[nt * 2 + 0];
                v[nt * 2 + 1] = (float)acc[mt][nt][half * 2 + 1] * fs * sbv[nt * 2 + 1];
            }
            float m = v[0];
            #pragma unroll
            for (int j = 1; j < 8; j++) m = fmaxf(m, v[j]);
            m = fmaxf(m, __shfl_xor_sync(0xffffffffu, m, 1));
            m = fmaxf(m, __shfl_xor_sync(0xffffffffu, m, 2));

            float l = 0.0f, msum = 0.0f;
            int cnt = 0;
            #pragma unroll
            for (int j = 0; j < 8; j++) {
                l += __expf(v[j] - m);
                const int gx = colb + (j >> 1) * 8 + (j & 1);
                const int cloc = wn * 32 + (j >> 1) * 8 + (lane & 3) * 2 + (j & 1);
                if (labB[cloc] == labr && gx != gy) { msum += v[j]; cnt++; }
            }
            l    += __shfl_xor_sync(0xffffffffu, l, 1);
            l    += __shfl_xor_sync(0xffffffffu, l, 2);
            msum += __shfl_xor_sync(0xffffffffu, msum, 1);
            msum += __shfl_xor_sync(0xffffffffu, msum, 2);
            cnt  += __shfl_xor_sync(0xffffffffu, cnt, 1);
            cnt  += __shfl_xor_sync(0xffffffffu, cnt, 2);

            if ((lane & 3) == 0) {
                const int idx = chunk * NN + gy;
                g_m[idx] = m; g_l[idx] = l; g_ms[idx] = msum; g_c[idx] = cnt;
            }
        }
    }
}

// ---------------- chunk merge + final loss ----------------
__global__ void reduce_rows(float* __restrict__ out)
{
    const int t = blockIdx.x * 256 + threadIdx.x;   // 65536 threads
    const int row = t >> 3;
    const int sub = t & 7;                          // 8 lanes per row, 32 chunks each
    const int c0 = sub * 32;

    float M = -CUDART_INF_F;
    #pragma unroll 8
    for (int c = 0; c < 32; c++)
        M = fmaxf(M, g_m[(c0 + c) * NN + row]);
    #pragma unroll
    for (int o = 1; o <= 4; o <<= 1)
        M = fmaxf(M, __shfl_xor_sync(0xffffffffu, M, o));

    float L = 0.0f, MS = 0.0f;
    int C = 0;
    #pragma unroll 8
    for (int c = 0; c < 32; c++) {
        const int i = (c0 + c) * NN + row;
        L  += g_l[i] * __expf(g_m[i] - M);
        MS += g_ms[i];
        C  += g_c[i];
    }
    #pragma unroll
    for (int o = 1; o <= 4; o <<= 1) {
        L  += __shfl_xor_sync(0xffffffffu, L,  o);
        MS += __shfl_xor_sync(0xffffffffu, MS, o);
        C  += __shfl_xor_sync(0xffffffffu, C,  o);
    }

    float val = 0.0f;
    if (sub == 0) {
        const float lse = M + logf(L);
        val = (C > 0) ? (MS / (float)C - lse) : 0.0f;
    }
    #pragma unroll
    for (int o = 16; o >= 1; o >>= 1)
        val += __shfl_xor_sync(0xffffffffu, val, o);

    __shared__ float sred[8];
    if ((threadIdx.x & 31) == 0) sred[threadIdx.x >> 5] = val;
    __syncthreads();
    if (threadIdx.x == 0) {
        float tsum = 0.0f;
        #pragma unroll
        for (int w = 0; w < 8; w++) tsum += sred[w];
        atomicAdd(out, -tsum / (float)NN);
    }
}

// ---------------- launch ----------------
extern "C" void kernel_launch(void* const* d_in, const int* in_sizes, int n_in,
                              void* d_out, int out_size)
{
    const float* image  = (const float*)d_in[0];
    const float* text   = (const float*)d_in[1];
    const float* scale  = (const float*)d_in[2];
    const void*  labels = d_in[3];
    float* out = (float*)d_out;

    cudaFuncSetAttribute(gemm_mma, cudaFuncAttributeMaxDynamicSharedMemorySize, SMEM_TOTAL);

    prep_labels<<<1, 256>>>(labels);
    zero_out<<<1, 32>>>(out);
    quant_s8<<<2048, 256>>>(image, text);

    dim3 grid(NN / BN, NN / BM);   // 64 x 64 tiles
    gemm_mma<<<grid, NTHREADS, SMEM_TOTAL>>>(scale);

    reduce_rows<<<256, 256>>>(out);
}

// round 8
// speedup vs baseline: 1.8991x; 1.8991x over previous
#include <cuda_runtime.h>
#include <cuda_fp16.h>
#include <math_constants.h>
#include <cstdint>

// Problem shape (fixed by the reference)
#define NN 8192
#define DD 512

// GEMM tiling
#define BM 128
#define BN 128
#define BK 64                 // f16 elements per smem stage
#define NKITER (DD / BK)      // 8
#define NTHREADS 256
#define NSTAGE 3
#define NCHUNK 256            // stats chunk width = 32 cols

// smem: 3 stages of 2 tiles (A,B), each 128 rows x 144 bytes (128B data + 16B pad)
#define ROWB 144
#define TILE_B (128 * ROWB)        // 18432
#define S_A 0
#define S_B TILE_B
#define STAGE_B (2 * TILE_B)       // 36864
#define SMEM_LAB_A 0               // 128 ints
#define SMEM_LAB_B 512
#define SMEM_STAGE0 1024
#define SMEM_TOTAL (SMEM_STAGE0 + NSTAGE * STAGE_B)   // 111616 (2 CTAs/SM)

// ---------------- device scratch (no cudaMalloc allowed) ----------------
__device__ __half gA[NN * DD];
__device__ __half gB[NN * DD];
__device__ float g_m [NCHUNK * NN];
__device__ float g_l [NCHUNK * NN];
__device__ float g_ms[NCHUNK * NN];
__device__ int   g_c [NCHUNK * NN];
__device__ int   g_lab[NN];

// ---------------- PTX helpers (baseline sm_80+ features only) ----------------
__device__ __forceinline__ uint32_t smem_u32(const void* p) {
    uint32_t a;
    asm("{ .reg .u64 t; cvta.to.shared.u64 t, %1; cvt.u32.u64 %0, t; }" : "=r"(a) : "l"(p));
    return a;
}
#define CPA16(dst, src) \
    asm volatile("cp.async.cg.shared.global [%0], [%1], 16;" :: "r"(dst), "l"(src))
#define CPA_COMMIT() asm volatile("cp.async.commit_group;" ::: "memory")
#define CPA_WAIT(n)  asm volatile("cp.async.wait_group %0;" :: "n"(n) : "memory")

__device__ __forceinline__ void ldsm4(uint32_t (&r)[4], uint32_t addr) {
    asm volatile("ldmatrix.sync.aligned.m8n8.x4.shared.b16 {%0,%1,%2,%3}, [%4];"
                 : "=r"(r[0]), "=r"(r[1]), "=r"(r[2]), "=r"(r[3]) : "r"(addr));
}
// f16 x f16 -> f16 accumulate (testing the 2x-rate hypothesis vs f32 accum)
__device__ __forceinline__ void mma_f16acc(uint32_t (&c)[2], const uint32_t (&a)[4],
                                           uint32_t b0, uint32_t b1) {
    asm volatile(
        "mma.sync.aligned.m16n8k16.row.col.f16.f16.f16.f16 "
        "{%0,%1}, {%2,%3,%4,%5}, {%6,%7}, {%0,%1};"
        : "+r"(c[0]), "+r"(c[1])
        : "r"(a[0]), "r"(a[1]), "r"(a[2]), "r"(a[3]), "r"(b0), "r"(b1));
}

// ---------------- label normalization + output zero (fused) ----------------
__global__ void prep_labels(const void* __restrict__ labels_raw, float* __restrict__ out) {
    __shared__ int s_is64;
    if (threadIdx.x == 0) {
        const unsigned long long* p = (const unsigned long long*)labels_raw;
        int is64 = 1;
        for (int w = 0; w < 32; w++)
            if ((p[w] >> 32) != 0ull) { is64 = 0; break; }
        s_is64 = is64;
        out[0] = 0.0f;
    }
    __syncthreads();
    const int is64 = s_is64;
    const long long* p64 = (const long long*)labels_raw;
    const int*       p32 = (const int*)labels_raw;
    for (int i = threadIdx.x; i < NN; i += blockDim.x)
        g_lab[i] = is64 ? (int)p64[i] : p32[i];
}

// ---------------- fp32 -> fp16 convert ----------------
__global__ void cvt_f16(const float* __restrict__ A, const float* __restrict__ B) {
    const int base = blockIdx.x * 256 + threadIdx.x;   // grid 2048 x 256
    #pragma unroll
    for (int i = 0; i < 4; i++) {
        int e = base + i * 524288;                     // 2 * 1048576 float4 total
        const float4* src;
        __half* dst;
        int off;
        if (e < 1048576) { src = (const float4*)A; off = e;           dst = gA; }
        else             { src = (const float4*)B; off = e - 1048576; dst = gB; }
        const float4 v = src[off];
        ((__half2*)dst)[off * 2 + 0] = __floats2half2_rn(v.x, v.y);
        ((__half2*)dst)[off * 2 + 1] = __floats2half2_rn(v.z, v.w);
    }
}

// ---------------- GEMM building blocks ----------------
__device__ __forceinline__ void load_stage(uint32_t sbase, int slot, int ki,
                                           int by, int bx, int tid) {
    const uint32_t stg = sbase + SMEM_STAGE0 + slot * STAGE_B;
    const int kb = ki * 128;          // byte offset within a 1024B feature row
    #pragma unroll
    for (int j = 0; j < 4; j++) {
        const int c = tid + j * 256;  // 0..1023
        const int r = c >> 3, q = c & 7;
        const uint32_t so = (uint32_t)(r * ROWB + q * 16);
        const size_t gAo = (size_t)(by * BM + r) * 1024 + kb + q * 16;
        const size_t gBo = (size_t)(bx * BN + r) * 1024 + kb + q * 16;
        CPA16(stg + S_A + so, (const char*)gA + gAo);
        CPA16(stg + S_B + so, (const char*)gB + gBo);
    }
}

// Warp tile 64(M) x 32(N); 4 k16-steps per stage; f16 accumulators within the
// stage (k=64 partials, |sum| << f16 range), promoted to fp32 once per stage.
__device__ __forceinline__ void compute_stage(uint32_t stg, int wm, int wn, int lane,
                                              float (&acc)[4][4][4]) {
    uint32_t cacc[4][4][2];
    #pragma unroll
    for (int mt = 0; mt < 4; mt++)
        #pragma unroll
        for (int nt = 0; nt < 4; nt++) { cacc[mt][nt][0] = 0u; cacc[mt][nt][1] = 0u; }

    #pragma unroll
    for (int ks = 0; ks < 4; ks++) {
        uint32_t a[4][4], b[2][4];
        const uint32_t a_lane = (uint32_t)((wm * 64 + (lane & 15)) * ROWB +
                                           ((lane >> 4) << 4) + ks * 32);
        #pragma unroll
        for (int mt = 0; mt < 4; mt++)
            ldsm4(a[mt], stg + S_A + a_lane + mt * 16 * ROWB);
        const uint32_t b_lane = (uint32_t)((wn * 32 + ((lane >> 4) & 1) * 8 + (lane & 7)) * ROWB +
                                           (((lane >> 3) & 1) << 4) + ks * 32);
        #pragma unroll
        for (int ntp = 0; ntp < 2; ntp++)
            ldsm4(b[ntp], stg + S_B + b_lane + ntp * 16 * ROWB);
        #pragma unroll
        for (int mt = 0; mt < 4; mt++)
            #pragma unroll
            for (int nt = 0; nt < 4; nt++) {
                const int ntp = nt >> 1, s2 = (nt & 1) * 2;
                mma_f16acc(cacc[mt][nt], a[mt], b[ntp][s2], b[ntp][s2 + 1]);
            }
    }

    // promote f16 stage-partials into fp32 master accumulators (FMA pipe, idle)
    #pragma unroll
    for (int mt = 0; mt < 4; mt++)
        #pragma unroll
        for (int nt = 0; nt < 4; nt++) {
            const float2 f0 = __half22float2(*(const __half2*)&cacc[mt][nt][0]);
            const float2 f1 = __half22float2(*(const __half2*)&cacc[mt][nt][1]);
            acc[mt][nt][0] += f0.x;
            acc[mt][nt][1] += f0.y;
            acc[mt][nt][2] += f1.x;
            acc[mt][nt][3] += f1.y;
        }
}

// ---------------- fused GEMM + stats ----------------
__global__ void __launch_bounds__(NTHREADS, 2)
gemm_mma(const float* __restrict__ scale_p)
{
    extern __shared__ char smem[];
    const uint32_t sbase = smem_u32(smem);
    const int tid = threadIdx.x;
    const int wid = tid >> 5, lane = tid & 31;
    const int wm = wid >> 2, wn = wid & 3;      // 2x4 warp grid, tile 64x32
    const int bx = blockIdx.x, by = blockIdx.y;

    int* labA = (int*)(smem + SMEM_LAB_A);
    int* labB = (int*)(smem + SMEM_LAB_B);
    if (tid < 128)       labA[tid] = g_lab[by * BM + tid];
    else                 labB[tid - 128] = g_lab[bx * BN + (tid - 128)];

    // prologue: 2 stages in flight
    load_stage(sbase, 0, 0, by, bx, tid); CPA_COMMIT();
    load_stage(sbase, 1, 1, by, bx, tid); CPA_COMMIT();

    float acc[4][4][4];
    #pragma unroll
    for (int a = 0; a < 4; a++)
        #pragma unroll
        for (int b = 0; b < 4; b++)
            #pragma unroll
            for (int e = 0; e < 4; e++) acc[a][b][e] = 0.0f;

    // single-sync 3-stage pipeline
    #pragma unroll 1
    for (int i = 0; i < NKITER; i++) {
        if (i < NKITER - 1) CPA_WAIT(1);
        else                CPA_WAIT(0);
        __syncthreads();
        if (i + 2 < NKITER) { load_stage(sbase, (i + 2) % NSTAGE, i + 2, by, bx, tid); CPA_COMMIT(); }
        compute_stage(sbase + SMEM_STAGE0 + (i % NSTAGE) * STAGE_B, wm, wn, lane, acc);
    }

    // ---------------- epilogue: per-row stats over this warp's 32 columns ----------------
    const float s = *scale_p;
    const int chunk = bx * 4 + wn;
    const int colb = bx * BN + wn * 32 + (lane & 3) * 2;

    #pragma unroll
    for (int mt = 0; mt < 4; mt++) {
        #pragma unroll
        for (int half = 0; half < 2; half++) {
            const int rloc = wm * 64 + mt * 16 + (lane >> 2) + half * 8;
            const int gy = by * BM + rloc;
            const int labr = labA[rloc];

            float v[8];
            #pragma unroll
            for (int nt = 0; nt < 4; nt++) {
                v[nt * 2 + 0] = acc[mt][nt][half * 2 + 0] * s;
                v[nt * 2 + 1] = acc[mt][nt][half * 2 + 1] * s;
            }
            float m = v[0];
            #pragma unroll
            for (int j = 1; j < 8; j++) m = fmaxf(m, v[j]);
            m = fmaxf(m, __shfl_xor_sync(0xffffffffu, m, 1));
            m = fmaxf(m, __shfl_xor_sync(0xffffffffu, m, 2));

            float l = 0.0f, msum = 0.0f;
            int cnt = 0;
            #pragma unroll
            for (int j = 0; j < 8; j++) {
                l += __expf(v[j] - m);
                const int gx = colb + (j >> 1) * 8 + (j & 1);
                const int cloc = wn * 32 + (j >> 1) * 8 + (lane & 3) * 2 + (j & 1);
                if (labB[cloc] == labr && gx != gy) { msum += v[j]; cnt++; }
            }
            l    += __shfl_xor_sync(0xffffffffu, l, 1);
            l    += __shfl_xor_sync(0xffffffffu, l, 2);
            msum += __shfl_xor_sync(0xffffffffu, msum, 1);
            msum += __shfl_xor_sync(0xffffffffu, msum, 2);
            cnt  += __shfl_xor_sync(0xffffffffu, cnt, 1);
            cnt  += __shfl_xor_sync(0xffffffffu, cnt, 2);

            if ((lane & 3) == 0) {
                const int idx = chunk * NN + gy;
                g_m[idx] = m; g_l[idx] = l; g_ms[idx] = msum; g_c[idx] = cnt;
            }
        }
    }
}

// ---------------- chunk merge + final loss ----------------
__global__ void reduce_rows(float* __restrict__ out)
{
    const int t = blockIdx.x * 256 + threadIdx.x;   // 65536 threads
    const int row = t >> 3;
    const int sub = t & 7;                          // 8 lanes per row, 32 chunks each
    const int c0 = sub * 32;

    float M = -CUDART_INF_F;
    #pragma unroll 8
    for (int c = 0; c < 32; c++)
        M = fmaxf(M, g_m[(c0 + c) * NN + row]);
    #pragma unroll
    for (int o = 1; o <= 4; o <<= 1)
        M = fmaxf(M, __shfl_xor_sync(0xffffffffu, M, o));

    float L = 0.0f, MS = 0.0f;
    int C = 0;
    #pragma unroll 8
    for (int c = 0; c < 32; c++) {
        const int i = (c0 + c) * NN + row;
        L  += g_l[i] * __expf(g_m[i] - M);
        MS += g_ms[i];
        C  += g_c[i];
    }
    #pragma unroll
    for (int o = 1; o <= 4; o <<= 1) {
        L  += __shfl_xor_sync(0xffffffffu, L,  o);
        MS += __shfl_xor_sync(0xffffffffu, MS, o);
        C  += __shfl_xor_sync(0xffffffffu, C,  o);
    }

    float val = 0.0f;
    if (sub == 0) {
        const float lse = M + logf(L);
        val = (C > 0) ? (MS / (float)C - lse) : 0.0f;
    }
    #pragma unroll
    for (int o = 16; o >= 1; o >>= 1)
        val += __shfl_xor_sync(0xffffffffu, val, o);

    __shared__ float sred[8];
    if ((threadIdx.x & 31) == 0) sred[threadIdx.x >> 5] = val;
    __syncthreads();
    if (threadIdx.x == 0) {
        float tsum = 0.0f;
        #pragma unroll
        for (int w = 0; w < 8; w++) tsum += sred[w];
        atomicAdd(out, -tsum / (float)NN);
    }
}

// ---------------- launch ----------------
extern "C" void kernel_launch(void* const* d_in, const int* in_sizes, int n_in,
                              void* d_out, int out_size)
{
    const float* image  = (const float*)d_in[0];
    const float* text   = (const float*)d_in[1];
    const float* scale  = (const float*)d_in[2];
    const void*  labels = d_in[3];
    float* out = (float*)d_out;

    cudaFuncSetAttribute(gemm_mma, cudaFuncAttributeMaxDynamicSharedMemorySize, SMEM_TOTAL);

    prep_labels<<<1, 256>>>(labels, out);
    cvt_f16<<<2048, 256>>>(image, text);

    dim3 grid(NN / BN, NN / BM);   // 64 x 64 tiles
    gemm_mma<<<grid, NTHREADS, SMEM_TOTAL>>>(scale);

    reduce_rows<<<256, 256>>>(out);
}

// round 9
// speedup vs baseline: 2.3026x; 1.2124x over previous
#include <cuda_runtime.h>
#include <cuda_bf16.h>
#include <math_constants.h>
#include <cstdint>

// Problem shape (fixed by the reference)
#define NN 8192
#define DD 512

// GEMM tiling
#define BM 128
#define BN 128
#define BK 64                 // bf16 elements per smem stage
#define NKITER (DD / BK)      // 8
#define NTHREADS 256
#define NSTAGE 3
#define NCHUNK 64             // stats chunk width = 128 cols (merged per CTA)

// smem: 3 stages of 2 tiles (A,B), each 128 rows x 144 bytes (128B data + 16B pad)
#define ROWB 144
#define TILE_B (128 * ROWB)        // 18432
#define S_A 0
#define S_B TILE_B
#define STAGE_B (2 * TILE_B)       // 36864
#define SMEM_LAB_A 0               // 128 ints
#define SMEM_LAB_B 512
#define SMEM_STAGE0 1024
#define SMEM_TOTAL (SMEM_STAGE0 + NSTAGE * STAGE_B)   // 111616 (2 CTAs/SM)

// ---------------- device scratch (no cudaMalloc allowed) ----------------
__device__ __nv_bfloat16 gA[NN * DD];
__device__ __nv_bfloat16 gB[NN * DD];
__device__ float g_m [NCHUNK * NN];
__device__ float g_l [NCHUNK * NN];
__device__ float g_ms[NCHUNK * NN];
__device__ int   g_c [NCHUNK * NN];
__device__ int   g_lab[NN];

// ---------------- PTX helpers (baseline sm_80+ features only) ----------------
__device__ __forceinline__ uint32_t smem_u32(const void* p) {
    uint32_t a;
    asm("{ .reg .u64 t; cvta.to.shared.u64 t, %1; cvt.u32.u64 %0, t; }" : "=r"(a) : "l"(p));
    return a;
}
#define CPA16(dst, src) \
    asm volatile("cp.async.cg.shared.global [%0], [%1], 16;" :: "r"(dst), "l"(src))
#define CPA_COMMIT() asm volatile("cp.async.commit_group;" ::: "memory")
#define CPA_WAIT(n)  asm volatile("cp.async.wait_group %0;" :: "n"(n) : "memory")

__device__ __forceinline__ void ldsm4(uint32_t (&r)[4], uint32_t addr) {
    asm volatile("ldmatrix.sync.aligned.m8n8.x4.shared.b16 {%0,%1,%2,%3}, [%4];"
                 : "=r"(r[0]), "=r"(r[1]), "=r"(r[2]), "=r"(r[3]) : "r"(addr));
}
__device__ __forceinline__ void mma_bf16(float (&c)[4], const uint32_t (&a)[4],
                                         uint32_t b0, uint32_t b1) {
    asm volatile(
        "mma.sync.aligned.m16n8k16.row.col.f32.bf16.bf16.f32 "
        "{%0,%1,%2,%3}, {%4,%5,%6,%7}, {%8,%9}, {%0,%1,%2,%3};"
        : "+f"(c[0]), "+f"(c[1]), "+f"(c[2]), "+f"(c[3])
        : "r"(a[0]), "r"(a[1]), "r"(a[2]), "r"(a[3]), "r"(b0), "r"(b1));
}

// ---------------- label normalization + output zero (fused) ----------------
__global__ void prep_labels(const void* __restrict__ labels_raw, float* __restrict__ out) {
    __shared__ int s_is64;
    if (threadIdx.x == 0) {
        const unsigned long long* p = (const unsigned long long*)labels_raw;
        int is64 = 1;
        for (int w = 0; w < 32; w++)
            if ((p[w] >> 32) != 0ull) { is64 = 0; break; }
        s_is64 = is64;
        out[0] = 0.0f;
    }
    __syncthreads();
    const int is64 = s_is64;
    const long long* p64 = (const long long*)labels_raw;
    const int*       p32 = (const int*)labels_raw;
    for (int i = threadIdx.x; i < NN; i += blockDim.x)
        g_lab[i] = is64 ? (int)p64[i] : p32[i];
}

// ---------------- fp32 -> bf16 convert ----------------
__global__ void cvt_bf16(const float* __restrict__ A, const float* __restrict__ B) {
    const int base = blockIdx.x * 256 + threadIdx.x;   // grid 2048 x 256
    #pragma unroll
    for (int i = 0; i < 4; i++) {
        int e = base + i * 524288;                     // 2 * 1048576 float4 total
        const float4* src;
        __nv_bfloat16* dst;
        int off;
        if (e < 1048576) { src = (const float4*)A; off = e;           dst = gA; }
        else             { src = (const float4*)B; off = e - 1048576; dst = gB; }
        const float4 v = src[off];
        ((__nv_bfloat162*)dst)[off * 2 + 0] =
            __nv_bfloat162(__float2bfloat16_rn(v.x), __float2bfloat16_rn(v.y));
        ((__nv_bfloat162*)dst)[off * 2 + 1] =
            __nv_bfloat162(__float2bfloat16_rn(v.z), __float2bfloat16_rn(v.w));
    }
}

// ---------------- GEMM building blocks ----------------
__device__ __forceinline__ void load_stage(uint32_t sbase, int slot, int ki,
                                           int by, int bx, int tid) {
    const uint32_t stg = sbase + SMEM_STAGE0 + slot * STAGE_B;
    const int kb = ki * 128;          // byte offset within a 1024B feature row
    #pragma unroll
    for (int j = 0; j < 4; j++) {
        const int c = tid + j * 256;  // 0..1023
        const int r = c >> 3, q = c & 7;
        const uint32_t so = (uint32_t)(r * ROWB + q * 16);
        const size_t gAo = (size_t)(by * BM + r) * 1024 + kb + q * 16;
        const size_t gBo = (size_t)(bx * BN + r) * 1024 + kb + q * 16;
        CPA16(stg + S_A + so, (const char*)gA + gAo);
        CPA16(stg + S_B + so, (const char*)gB + gBo);
    }
}

// Warp tile 64(M) x 32(N); 4 k16-steps per stage; 16 MMA per ks.
__device__ __forceinline__ void compute_stage(uint32_t stg, int wm, int wn, int lane,
                                              float (&acc)[4][4][4]) {
    #pragma unroll
    for (int ks = 0; ks < 4; ks++) {
        uint32_t a[4][4], b[2][4];
        const uint32_t a_lane = (uint32_t)((wm * 64 + (lane & 15)) * ROWB +
                                           ((lane >> 4) << 4) + ks * 32);
        #pragma unroll
        for (int mt = 0; mt < 4; mt++)
            ldsm4(a[mt], stg + S_A + a_lane + mt * 16 * ROWB);
        const uint32_t b_lane = (uint32_t)((wn * 32 + ((lane >> 4) & 1) * 8 + (lane & 7)) * ROWB +
                                           (((lane >> 3) & 1) << 4) + ks * 32);
        #pragma unroll
        for (int ntp = 0; ntp < 2; ntp++)
            ldsm4(b[ntp], stg + S_B + b_lane + ntp * 16 * ROWB);
        #pragma unroll
        for (int mt = 0; mt < 4; mt++)
            #pragma unroll
            for (int nt = 0; nt < 4; nt++) {
                const int ntp = nt >> 1, s2 = (nt & 1) * 2;
                mma_bf16(acc[mt][nt], a[mt], b[ntp][s2], b[ntp][s2 + 1]);
            }
    }
}

// ---------------- fused GEMM + stats ----------------
__global__ void __launch_bounds__(NTHREADS, 2)
gemm_mma(const float* __restrict__ scale_p)
{
    extern __shared__ char smem[];
    const uint32_t sbase = smem_u32(smem);
    const int tid = threadIdx.x;
    const int wid = tid >> 5, lane = tid & 31;
    const int wm = wid >> 2, wn = wid & 3;      // 2x4 warp grid, tile 64x32
    const int bx = blockIdx.x, by = blockIdx.y;

    int* labA = (int*)(smem + SMEM_LAB_A);
    int* labB = (int*)(smem + SMEM_LAB_B);
    if (tid < 128)       labA[tid] = g_lab[by * BM + tid];
    else                 labB[tid - 128] = g_lab[bx * BN + (tid - 128)];

    // prologue: 2 stages in flight
    load_stage(sbase, 0, 0, by, bx, tid); CPA_COMMIT();
    load_stage(sbase, 1, 1, by, bx, tid); CPA_COMMIT();

    float acc[4][4][4];
    #pragma unroll
    for (int a = 0; a < 4; a++)
        #pragma unroll
        for (int b = 0; b < 4; b++)
            #pragma unroll
            for (int e = 0; e < 4; e++) acc[a][b][e] = 0.0f;

    // single-sync 3-stage pipeline
    #pragma unroll 1
    for (int i = 0; i < NKITER; i++) {
        if (i < NKITER - 1) CPA_WAIT(1);
        else                CPA_WAIT(0);
        __syncthreads();
        if (i + 2 < NKITER) { load_stage(sbase, (i + 2) % NSTAGE, i + 2, by, bx, tid); CPA_COMMIT(); }
        compute_stage(sbase + SMEM_STAGE0 + (i % NSTAGE) * STAGE_B, wm, wn, lane, acc);
    }

    // ---------------- epilogue: per-row stats, merged across all 128 cols ----------------
    const float s = *scale_p;
    const int colb = bx * BN + wn * 32 + (lane & 3) * 2;

    __syncthreads();   // pipeline drained; safe to reuse stage smem for the merge table
    float4* tab = (float4*)(smem + SMEM_STAGE0);   // [128 rows][4 wn] of (m,l,ms,c)

    #pragma unroll
    for (int mt = 0; mt < 4; mt++) {
        #pragma unroll
        for (int half = 0; half < 2; half++) {
            const int rloc = wm * 64 + mt * 16 + (lane >> 2) + half * 8;
            const int gy = by * BM + rloc;
            const int labr = labA[rloc];

            float v[8];
            #pragma unroll
            for (int nt = 0; nt < 4; nt++) {
                v[nt * 2 + 0] = acc[mt][nt][half * 2 + 0] * s;
                v[nt * 2 + 1] = acc[mt][nt][half * 2 + 1] * s;
            }
            float m = v[0];
            #pragma unroll
            for (int j = 1; j < 8; j++) m = fmaxf(m, v[j]);
            m = fmaxf(m, __shfl_xor_sync(0xffffffffu, m, 1));
            m = fmaxf(m, __shfl_xor_sync(0xffffffffu, m, 2));

            float l = 0.0f, msum = 0.0f;
            int cnt = 0;
            #pragma unroll
            for (int j = 0; j < 8; j++) {
                l += __expf(v[j] - m);
                const int gx = colb + (j >> 1) * 8 + (j & 1);
                const int cloc = wn * 32 + (j >> 1) * 8 + (lane & 3) * 2 + (j & 1);
                if (labB[cloc] == labr && gx != gy) { msum += v[j]; cnt++; }
            }
            l    += __shfl_xor_sync(0xffffffffu, l, 1);
            l    += __shfl_xor_sync(0xffffffffu, l, 2);
            msum += __shfl_xor_sync(0xffffffffu, msum, 1);
            msum += __shfl_xor_sync(0xffffffffu, msum, 2);
            cnt  += __shfl_xor_sync(0xffffffffu, cnt, 1);
            cnt  += __shfl_xor_sync(0xffffffffu, cnt, 2);

            if ((lane & 3) == 0)
                tab[rloc * 4 + wn] = make_float4(m, l, msum, (float)cnt);
        }
    }
    __syncthreads();

    // one record per row per CTA (chunk = bx)
    if (tid < 128) {
        const float4 e0 = tab[tid * 4 + 0];
        const float4 e1 = tab[tid * 4 + 1];
        const float4 e2 = tab[tid * 4 + 2];
        const float4 e3 = tab[tid * 4 + 3];
        const float M = fmaxf(fmaxf(e0.x, e1.x), fmaxf(e2.x, e3.x));
        const float L = e0.y * __expf(e0.x - M) + e1.y * __expf(e1.x - M) +
                        e2.y * __expf(e2.x - M) + e3.y * __expf(e3.x - M);
        const float MS = e0.z + e1.z + e2.z + e3.z;
        const int   C  = (int)(e0.w + e1.w + e2.w + e3.w);
        const int idx = bx * NN + by * BM + tid;
        g_m[idx] = M; g_l[idx] = L; g_ms[idx] = MS; g_c[idx] = C;
    }
}

// ---------------- chunk merge + final loss ----------------
__global__ void reduce_rows(float* __restrict__ out)
{
    const int t = blockIdx.x * 256 + threadIdx.x;   // 32768 threads (grid 128)
    const int row = t >> 2;
    const int sub = t & 3;                          // 4 lanes per row, 16 chunks each
    const int c0 = sub * 16;

    float M = -CUDART_INF_F;
    #pragma unroll 8
    for (int c = 0; c < 16; c++)
        M = fmaxf(M, g_m[(c0 + c) * NN + row]);
    M = fmaxf(M, __shfl_xor_sync(0xffffffffu, M, 1));
    M = fmaxf(M, __shfl_xor_sync(0xffffffffu, M, 2));

    float L = 0.0f, MS = 0.0f;
    int C = 0;
    #pragma unroll 8
    for (int c = 0; c < 16; c++) {
        const int i = (c0 + c) * NN + row;
        L  += g_l[i] * __expf(g_m[i] - M);
        MS += g_ms[i];
        C  += g_c[i];
    }
    #pragma unroll
    for (int o = 1; o <= 2; o <<= 1) {
        L  += __shfl_xor_sync(0xffffffffu, L,  o);
        MS += __shfl_xor_sync(0xffffffffu, MS, o);
        C  += __shfl_xor_sync(0xffffffffu, C,  o);
    }

    float val = 0.0f;
    if (sub == 0) {
        const float lse = M + logf(L);
        val = (C > 0) ? (MS / (float)C - lse) : 0.0f;
    }
    #pragma unroll
    for (int o = 16; o >= 1; o >>= 1)
        val += __shfl_xor_sync(0xffffffffu, val, o);

    __shared__ float sred[8];
    if ((threadIdx.x & 31) == 0) sred[threadIdx.x >> 5] = val;
    __syncthreads();
    if (threadIdx.x == 0) {
        float tsum = 0.0f;
        #pragma unroll
        for (int w = 0; w < 8; w++) tsum += sred[w];
        atomicAdd(out, -tsum / (float)NN);
    }
}

// ---------------- launch ----------------
extern "C" void kernel_launch(void* const* d_in, const int* in_sizes, int n_in,
                              void* d_out, int out_size)
{
    const float* image  = (const float*)d_in[0];
    const float* text   = (const float*)d_in[1];
    const float* scale  = (const float*)d_in[2];
    const void*  labels = d_in[3];
    float* out = (float*)d_out;

    cudaFuncSetAttribute(gemm_mma, cudaFuncAttributeMaxDynamicSharedMemorySize, SMEM_TOTAL);

    prep_labels<<<1, 256>>>(labels, out);
    cvt_bf16<<<2048, 256>>>(image, text);

    dim3 grid(NN / BN, NN / BM);   // 64 x 64 tiles
    gemm_mma<<<grid, NTHREADS, SMEM_TOTAL>>>(scale);

    reduce_rows<<<128, 256>>>(out);
}

// round 10
// speedup vs baseline: 2.3187x; 1.0070x over previous
#include <cuda_runtime.h>
#include <cuda_bf16.h>
#include <math_constants.h>
#include <cstdint>

// Problem shape (fixed by the reference)
#define NN 8192
#define DD 512

// GEMM tiling
#define BM 128
#define BN 128
#define BK 64                 // bf16 elements per smem stage
#define NKITER (DD / BK)      // 8
#define NTHREADS 256
#define NSTAGE 3
#define NCHUNK 64             // stats chunk width = 128 cols (merged per CTA)

// smem: 3 stages of 2 tiles (A,B), each 128 rows x 144 bytes (128B data + 16B pad)
#define ROWB 144
#define TILE_B (128 * ROWB)        // 18432
#define S_A 0
#define S_B TILE_B
#define STAGE_B (2 * TILE_B)       // 36864
#define SMEM_LAB_A 0               // 128 ints
#define SMEM_LAB_B 512
#define SMEM_STAGE0 1024
#define SMEM_TOTAL (SMEM_STAGE0 + NSTAGE * STAGE_B)   // 111616 (2 CTAs/SM)

// ---------------- device scratch (no cudaMalloc allowed) ----------------
__device__ __nv_bfloat16 gA[NN * DD];
__device__ __nv_bfloat16 gB[NN * DD];
__device__ float4 g_rec[NN * NCHUNK];   // (m, l, masked_sum, count) per (row, chunk)
__device__ int    g_lab[NN];

// ---------------- PTX helpers (baseline sm_80+ features only) ----------------
__device__ __forceinline__ uint32_t smem_u32(const void* p) {
    uint32_t a;
    asm("{ .reg .u64 t; cvta.to.shared.u64 t, %1; cvt.u32.u64 %0, t; }" : "=r"(a) : "l"(p));
    return a;
}
#define CPA16(dst, src) \
    asm volatile("cp.async.cg.shared.global [%0], [%1], 16;" :: "r"(dst), "l"(src))
#define CPA_COMMIT() asm volatile("cp.async.commit_group;" ::: "memory")
#define CPA_WAIT(n)  asm volatile("cp.async.wait_group %0;" :: "n"(n) : "memory")

__device__ __forceinline__ void ldsm4(uint32_t (&r)[4], uint32_t addr) {
    asm volatile("ldmatrix.sync.aligned.m8n8.x4.shared.b16 {%0,%1,%2,%3}, [%4];"
                 : "=r"(r[0]), "=r"(r[1]), "=r"(r[2]), "=r"(r[3]) : "r"(addr));
}
__device__ __forceinline__ void mma_bf16(float (&c)[4], const uint32_t (&a)[4],
                                         uint32_t b0, uint32_t b1) {
    asm volatile(
        "mma.sync.aligned.m16n8k16.row.col.f32.bf16.bf16.f32 "
        "{%0,%1,%2,%3}, {%4,%5,%6,%7}, {%8,%9}, {%0,%1,%2,%3};"
        : "+f"(c[0]), "+f"(c[1]), "+f"(c[2]), "+f"(c[3])
        : "r"(a[0]), "r"(a[1]), "r"(a[2]), "r"(a[3]), "r"(b0), "r"(b1));
}

// ---------------- fp32 -> bf16 convert + fused label prep ----------------
// Blocks 0..2047: convert. Block 2048: label normalization + output zero.
__global__ void cvt_bf16(const float* __restrict__ A, const float* __restrict__ B,
                         const void* __restrict__ labels_raw, float* __restrict__ out) {
    if (blockIdx.x == 2048) {
        __shared__ int s_is64;
        if (threadIdx.x == 0) {
            const unsigned long long* p = (const unsigned long long*)labels_raw;
            int is64 = 1;
            for (int w = 0; w < 32; w++)
                if ((p[w] >> 32) != 0ull) { is64 = 0; break; }
            s_is64 = is64;
            out[0] = 0.0f;
        }
        __syncthreads();
        const int is64 = s_is64;
        const long long* p64 = (const long long*)labels_raw;
        const int*       p32 = (const int*)labels_raw;
        for (int i = threadIdx.x; i < NN; i += blockDim.x)
            g_lab[i] = is64 ? (int)p64[i] : p32[i];
        return;
    }
    const int base = blockIdx.x * 256 + threadIdx.x;
    #pragma unroll
    for (int i = 0; i < 4; i++) {
        int e = base + i * 524288;                     // 2 * 1048576 float4 total
        const float4* src;
        __nv_bfloat16* dst;
        int off;
        if (e < 1048576) { src = (const float4*)A; off = e;           dst = gA; }
        else             { src = (const float4*)B; off = e - 1048576; dst = gB; }
        const float4 v = src[off];
        ((__nv_bfloat162*)dst)[off * 2 + 0] =
            __nv_bfloat162(__float2bfloat16_rn(v.x), __float2bfloat16_rn(v.y));
        ((__nv_bfloat162*)dst)[off * 2 + 1] =
            __nv_bfloat162(__float2bfloat16_rn(v.z), __float2bfloat16_rn(v.w));
    }
}

// ---------------- GEMM building blocks ----------------
__device__ __forceinline__ void load_stage(uint32_t sbase, int slot, int ki,
                                           int by, int bx, int tid) {
    const uint32_t stg = sbase + SMEM_STAGE0 + slot * STAGE_B;
    const int kb = ki * 128;          // byte offset within a 1024B feature row
    #pragma unroll
    for (int j = 0; j < 4; j++) {
        const int c = tid + j * 256;  // 0..1023
        const int r = c >> 3, q = c & 7;
        const uint32_t so = (uint32_t)(r * ROWB + q * 16);
        const size_t gAo = (size_t)(by * BM + r) * 1024 + kb + q * 16;
        const size_t gBo = (size_t)(bx * BN + r) * 1024 + kb + q * 16;
        CPA16(stg + S_A + so, (const char*)gA + gAo);
        CPA16(stg + S_B + so, (const char*)gB + gBo);
    }
}

// Warp tile 64(M) x 32(N); 4 k16-steps per stage; 16 MMA per ks.
__device__ __forceinline__ void compute_stage(uint32_t stg, int wm, int wn, int lane,
                                              float (&acc)[4][4][4]) {
    #pragma unroll
    for (int ks = 0; ks < 4; ks++) {
        uint32_t a[4][4], b[2][4];
        const uint32_t a_lane = (uint32_t)((wm * 64 + (lane & 15)) * ROWB +
                                           ((lane >> 4) << 4) + ks * 32);
        #pragma unroll
        for (int mt = 0; mt < 4; mt++)
            ldsm4(a[mt], stg + S_A + a_lane + mt * 16 * ROWB);
        const uint32_t b_lane = (uint32_t)((wn * 32 + ((lane >> 4) & 1) * 8 + (lane & 7)) * ROWB +
                                           (((lane >> 3) & 1) << 4) + ks * 32);
        #pragma unroll
        for (int ntp = 0; ntp < 2; ntp++)
            ldsm4(b[ntp], stg + S_B + b_lane + ntp * 16 * ROWB);
        #pragma unroll
        for (int mt = 0; mt < 4; mt++)
            #pragma unroll
            for (int nt = 0; nt < 4; nt++) {
                const int ntp = nt >> 1, s2 = (nt & 1) * 2;
                mma_bf16(acc[mt][nt], a[mt], b[ntp][s2], b[ntp][s2 + 1]);
            }
    }
}

// ---------------- fused GEMM + stats ----------------
__global__ void __launch_bounds__(NTHREADS, 2)
gemm_mma(const float* __restrict__ scale_p)
{
    extern __shared__ char smem[];
    const uint32_t sbase = smem_u32(smem);
    const int tid = threadIdx.x;
    const int wid = tid >> 5, lane = tid & 31;
    const int wm = wid >> 2, wn = wid & 3;      // 2x4 warp grid, tile 64x32
    const int bx = blockIdx.x, by = blockIdx.y;

    int* labA = (int*)(smem + SMEM_LAB_A);
    int* labB = (int*)(smem + SMEM_LAB_B);
    if (tid < 128)       labA[tid] = g_lab[by * BM + tid];
    else                 labB[tid - 128] = g_lab[bx * BN + (tid - 128)];

    // prologue: 2 stages in flight
    load_stage(sbase, 0, 0, by, bx, tid); CPA_COMMIT();
    load_stage(sbase, 1, 1, by, bx, tid); CPA_COMMIT();

    float acc[4][4][4];
    #pragma unroll
    for (int a = 0; a < 4; a++)
        #pragma unroll
        for (int b = 0; b < 4; b++)
            #pragma unroll
            for (int e = 0; e < 4; e++) acc[a][b][e] = 0.0f;

    // single-sync 3-stage pipeline
    #pragma unroll 1
    for (int i = 0; i < NKITER; i++) {
        if (i < NKITER - 1) CPA_WAIT(1);
        else                CPA_WAIT(0);
        __syncthreads();
        if (i + 2 < NKITER) { load_stage(sbase, (i + 2) % NSTAGE, i + 2, by, bx, tid); CPA_COMMIT(); }
        compute_stage(sbase + SMEM_STAGE0 + (i % NSTAGE) * STAGE_B, wm, wn, lane, acc);
    }

    // ---------------- epilogue: per-row stats, merged across all 128 cols ----------------
    const float s = *scale_p;
    const int colb = bx * BN + wn * 32 + (lane & 3) * 2;

    __syncthreads();   // pipeline drained; safe to reuse stage smem for the merge table
    float4* tab = (float4*)(smem + SMEM_STAGE0);   // [128 rows][4 wn] of (m,l,ms,c)

    #pragma unroll
    for (int mt = 0; mt < 4; mt++) {
        #pragma unroll
        for (int half = 0; half < 2; half++) {
            const int rloc = wm * 64 + mt * 16 + (lane >> 2) + half * 8;
            const int gy = by * BM + rloc;
            const int labr = labA[rloc];

            float v[8];
            #pragma unroll
            for (int nt = 0; nt < 4; nt++) {
                v[nt * 2 + 0] = acc[mt][nt][half * 2 + 0] * s;
                v[nt * 2 + 1] = acc[mt][nt][half * 2 + 1] * s;
            }
            float m = v[0];
            #pragma unroll
            for (int j = 1; j < 8; j++) m = fmaxf(m, v[j]);
            m = fmaxf(m, __shfl_xor_sync(0xffffffffu, m, 1));
            m = fmaxf(m, __shfl_xor_sync(0xffffffffu, m, 2));

            float l = 0.0f, msum = 0.0f;
            int cnt = 0;
            #pragma unroll
            for (int j = 0; j < 8; j++) {
                l += __expf(v[j] - m);
                const int gx = colb + (j >> 1) * 8 + (j & 1);
                const int cloc = wn * 32 + (j >> 1) * 8 + (lane & 3) * 2 + (j & 1);
                if (labB[cloc] == labr && gx != gy) { msum += v[j]; cnt++; }
            }
            l    += __shfl_xor_sync(0xffffffffu, l, 1);
            l    += __shfl_xor_sync(0xffffffffu, l, 2);
            msum += __shfl_xor_sync(0xffffffffu, msum, 1);
            msum += __shfl_xor_sync(0xffffffffu, msum, 2);
            cnt  += __shfl_xor_sync(0xffffffffu, cnt, 1);
            cnt  += __shfl_xor_sync(0xffffffffu, cnt, 2);

            if ((lane & 3) == 0)
                tab[rloc * 4 + wn] = make_float4(m, l, msum, (float)cnt);
        }
    }
    __syncthreads();

    // one record per row per CTA (chunk = bx), AoS layout for coalesced reduce reads
    if (tid < 128) {
        const float4 e0 = tab[tid * 4 + 0];
        const float4 e1 = tab[tid * 4 + 1];
        const float4 e2 = tab[tid * 4 + 2];
        const float4 e3 = tab[tid * 4 + 3];
        const float M = fmaxf(fmaxf(e0.x, e1.x), fmaxf(e2.x, e3.x));
        const float L = e0.y * __expf(e0.x - M) + e1.y * __expf(e1.x - M) +
                        e2.y * __expf(e2.x - M) + e3.y * __expf(e3.x - M);
        const float MS = e0.z + e1.z + e2.z + e3.z;
        const float C  = e0.w + e1.w + e2.w + e3.w;
        g_rec[(by * BM + tid) * NCHUNK + bx] = make_float4(M, L, MS, C);
    }
}

// ---------------- chunk merge + final loss (1 warp per row) ----------------
__global__ void reduce_rows(float* __restrict__ out)
{
    const int row  = blockIdx.x * 8 + (threadIdx.x >> 5);   // grid 1024 x 256
    const int lane = threadIdx.x & 31;

    const float4 r1 = g_rec[row * NCHUNK + lane];
    const float4 r2 = g_rec[row * NCHUNK + 32 + lane];

    float M = fmaxf(r1.x, r2.x);
    float L = r1.y * __expf(r1.x - M) + r2.y * __expf(r2.x - M);
    float MS = r1.z + r2.z;
    float C  = r1.w + r2.w;

    #pragma unroll
    for (int o = 16; o >= 1; o >>= 1) {
        const float Mo  = __shfl_xor_sync(0xffffffffu, M,  o);
        const float Lo  = __shfl_xor_sync(0xffffffffu, L,  o);
        const float MSo = __shfl_xor_sync(0xffffffffu, MS, o);
        const float Co  = __shfl_xor_sync(0xffffffffu, C,  o);
        const float Mn = fmaxf(M, Mo);
        L = L * __expf(M - Mn) + Lo * __expf(Mo - Mn);
        M = Mn; MS += MSo; C += Co;
    }

    float val = 0.0f;
    if (lane == 0) {
        const float lse = M + logf(L);
        val = (C > 0.5f) ? (MS / C - lse) : 0.0f;
    }

    __shared__ float sred[8];
    if (lane == 0) sred[threadIdx.x >> 5] = val;
    __syncthreads();
    if (threadIdx.x == 0) {
        float tsum = 0.0f;
        #pragma unroll
        for (int w = 0; w < 8; w++) tsum += sred[w];
        atomicAdd(out, -tsum / (float)NN);
    }
}

// ---------------- launch ----------------
extern "C" void kernel_launch(void* const* d_in, const int* in_sizes, int n_in,
                              void* d_out, int out_size)
{
    const float* image  = (const float*)d_in[0];
    const float* text   = (const float*)d_in[1];
    const float* scale  = (const float*)d_in[2];
    const void*  labels = d_in[3];
    float* out = (float*)d_out;

    cudaFuncSetAttribute(gemm_mma, cudaFuncAttributeMaxDynamicSharedMemorySize, SMEM_TOTAL);

    cvt_bf16<<<2049, 256>>>(image, text, labels, out);

    dim3 grid(NN / BN, NN / BM);   // 64 x 64 tiles
    gemm_mma<<<grid, NTHREADS, SMEM_TOTAL>>>(scale);

    reduce_rows<<<1024, 256>>>(out);
}